// round 16
// baseline (speedup 1.0000x reference)
#include <cuda_runtime.h>
#include <math.h>

#define BN   64
#define PAST 128
#define FUT  64
#define NF   51
#define NO   50
#define NH   4
#define N1   (BN*PAST)   /* 8192 */
#define N2   (BN*FUT)    /* 4096 */
#define E1N  (N1*16)
#define E2N  (N2*16)
#define T1   (E1N+N1)    /* 139264 */
#define T2   (E2N+N2)    /* 69632 */
#define PAD  64          /* bucket slots per node (max degree ~34) */
#define G1B  (N1/16)     /* 512 gemm blocks */
#define X2B  (N2/16)     /* 256 x2-pre blocks */
#define MB   4
#define SCB  ((T1+T2+255)/256)   /* 816 scatter blocks */
#define AGRID (G1B + SCB + X2B + MB + 1)
#define DGRID 512
#define Z2PB 20
#define Z2B  ((N2+Z2PB-1)/Z2PB)  /* 205 */

// ---------------- scratch ----------------
__device__ float d_y  [N1];
__device__ float d_x2 [N2*NO];
__device__ float d_h1 [N1*NH*NO];
__device__ __align__(16) float d_as1[N1*NH];
__device__ __align__(16) float d_ad1[N1*NH];
__device__ float d_x1o[N1*NO];
__device__ float d_M  [NO*NO];
__device__ float d_q1h[N1];
__device__ float d_z2 [N2*NO];
__device__ __align__(16) float d_h2 [N2*NH];
__device__ __align__(16) float d_as2[N2*NH];
__device__ __align__(16) float d_ad2[N2*NH];
__device__ unsigned d_maskw[FUT*4];
__device__ int d_cur1[N1];           // zero at load; consumer restores per call
__device__ int d_csr1[N1*PAD];       // padded buckets
__device__ int d_cur2[N2];
__device__ int d_csr2[N2*PAD];

// grid barrier (monotonic flag: replay-safe). Used only by kD.
__device__ unsigned g_barcnt = 0;
__device__ unsigned g_barflag = 0;

__device__ __forceinline__ void grid_barrier() {
    __syncthreads();
    if (threadIdx.x == 0) {
        unsigned old = *((volatile unsigned*)&g_barflag);
        __threadfence();
        unsigned a = atomicAdd(&g_barcnt, 1u);
        if (a == gridDim.x - 1) {
            atomicExch(&g_barcnt, 0u);
            __threadfence();
            atomicExch(&g_barflag, old + 1u);
        } else {
            while (*((volatile unsigned*)&g_barflag) == old) __nanosleep(64);
        }
        __threadfence();
    }
    __syncthreads();
}

__device__ __forceinline__ float warp_sum(float v) {
    #pragma unroll
    for (int o = 16; o; o >>= 1) v += __shfl_xor_sync(0xffffffffu, v, o);
    return v;
}
__device__ __forceinline__ float lrelu(float x) { return x > 0.f ? x : 0.2f * x; }

// ========== A: gemm | scatter | x2 pre | M | mask (all mutually independent) ==========
__global__ void kA(const int* __restrict__ cat1, const float* __restrict__ num1,
                   const int* __restrict__ cat2, const float* __restrict__ num2,
                   const int* __restrict__ e1,   const int* __restrict__ e2,
                   const int* __restrict__ A,
                   const float* __restrict__ e0w, const float* __restrict__ e1w,
                   const float* __restrict__ e2w,
                   const float* __restrict__ lin, const float* __restrict__ asrc,
                   const float* __restrict__ adst, const float* __restrict__ W) {
    int bb = blockIdx.x, t = threadIdx.x;
    if (bb < G1B) {
        __shared__ float xs[16*NF];
        __shared__ float hs[16*NH*NO];
        int n0 = bb*16;
        for (int idx = t; idx < 16*NF; idx += 256) {
            int j = idx / NF, k = idx % NF, n = n0 + j;
            float v;
            if      (k < 16) v = e0w[cat1[n*3+0]*16 + k];
            else if (k < 24) v = e1w[cat1[n*3+1]*8  + (k-16)];
            else if (k < 48) v = e2w[cat1[n*3+2]*24 + (k-24)];
            else             v = num1[n*3 + (k-48)];
            xs[idx] = v;
            if (k == NF-1) d_y[n] = v;
        }
        __syncthreads();
        if (t < NH*NO) {
            float acc[16];
            #pragma unroll
            for (int j = 0; j < 16; j++) acc[j] = 0.f;
            for (int k = 0; k < NF; k++) {
                float l = __ldg(&lin[k*(NH*NO) + t]);
                #pragma unroll
                for (int j = 0; j < 16; j++) acc[j] += xs[j*NF + k] * l;
            }
            #pragma unroll
            for (int j = 0; j < 16; j++) {
                d_h1[(n0+j)*(NH*NO) + t] = acc[j];
                hs[j*(NH*NO) + t] = acc[j];
            }
        }
        __syncthreads();
        if (t < 128) {
            int j = t >> 3, r = t & 7, head = r & 3;
            const float* att = (r < 4) ? asrc : adst;
            float a = 0.f;
            #pragma unroll
            for (int c = 0; c < NO; c++)
                a += hs[j*(NH*NO) + head*NO + c] * att[head*NO + c];
            if (r < 4) d_as1[(n0+j)*NH + head] = a;
            else       d_ad1[(n0+j)*NH + head] = a;
        }
        return;
    }
    bb -= G1B;
    if (bb < SCB) {
        // padded-bucket scatter (inputs only)
        int i = bb*256 + t;
        if (i < T1) {
            int s, d;
            if (i < E1N) { s = e1[i]; d = e1[E1N + i]; }
            else         { s = d = i - E1N; }
            int pos = atomicAdd(&d_cur1[d], 1);
            d_csr1[d*PAD + pos] = s;
        } else {
            int j = i - T1;
            if (j < T2) {
                int s, d;
                if (j < E2N) { s = e2[j]; d = e2[E2N + j]; }
                else         { s = d = j - E2N; }
                int pos = atomicAdd(&d_cur2[d], 1);
                d_csr2[d*PAD + pos] = s;
            }
        }
        return;
    }
    bb -= SCB;
    if (bb < X2B) {
        int base = bb*16;
        for (int idx = t; idx < 16*NO; idx += 256) {
            int ln = idx / NO, c = idx % NO;
            int n = base + ln;
            float v;
            if      (c < 16) v = e0w[cat2[n*3+0]*16 + c];
            else if (c < 24) v = e1w[cat2[n*3+1]*8  + (c-16)];
            else if (c < 48) v = e2w[cat2[n*3+2]*24 + (c-24)];
            else             v = num2[n*3 + (c-48)];
            d_x2[n*NO + c] = v;
        }
        return;
    }
    bb -= X2B;
    if (bb < MB) {
        int lo = bb*625, hi = lo + 625;
        for (int idx = lo + t; idx < hi; idx += 256) {
            int i = idx / NO, j = idx % NO;
            float s = 0.f;
            #pragma unroll
            for (int k = 0; k < 64; k++) s += __ldg(&W[i*64+k]) * __ldg(&W[j*64+k]);
            d_M[idx] = 2.f * s;
        }
        return;
    }
    {
        int f = t >> 2, wd = t & 3;
        unsigned u = 0;
        for (int i = 0; i < 32; i++)
            if (A[(wd*32+i)*(PAST+FUT) + PAST + f]) u |= (1u << i);
        d_maskw[f*4 + wd] = u;
    }
}

// ==== C: GAT1 aggregate (blocks < N1) | z2 = M @ x2 (extra blocks) ====
__global__ void kAgg1(const float* __restrict__ bias) {
    __shared__ float sbuf[NO*NO + Z2PB*NO];   // 14 KB union
    int n = blockIdx.x;
    int t = threadIdx.x;

    if (n >= N1) {
        int base = (n - N1) * Z2PB;
        float* Ms  = sbuf;
        float* x2s = sbuf + NO*NO;
        for (int idx = t; idx < NO*NO; idx += 256) Ms[idx] = d_M[idx];
        for (int idx = t; idx < Z2PB*NO; idx += 256) {
            int gl = base*NO + idx;
            x2s[idx] = (gl < N2*NO) ? d_x2[gl] : 0.f;
        }
        __syncthreads();
        for (int idx = t; idx < Z2PB*NO; idx += 256) {
            int ln = idx / NO, c = idx % NO;
            int node = base + ln;
            if (node < N2) {
                float z = 0.f;
                #pragma unroll
                for (int j = 0; j < NO; j++) z += Ms[c*NO + j] * x2s[ln*NO + j];
                d_z2[node*NO + c] = z;
            }
        }
        return;
    }

    int wp = t >> 5;
    int w  = wp >> 1;
    int eh = wp & 1;
    int lane = t & 31;
    int beg = n*PAD;
    int end = beg + d_cur1[n];     // degree count from scatter
    float ad = d_ad1[n*NH + w];

    float* so      = sbuf;          // 50
    float* ssum_sh = sbuf + 64;     // 4
    float* red     = sbuf + 96;     // 256
    if (t < NO) so[t] = 0.f;
    if (t < NH) ssum_sh[t] = 0.f;
    __syncthreads();
    if (t == 0) d_cur1[n] = 0;      // restore for next replay

    float ssum = 0.f, a0 = 0.f, a1 = 0.f, b0 = 0.f, b1 = 0.f;
    int c0 = lane, c1 = lane + 32;
    bool has1 = (c1 < NO);
    int i = beg + eh;
    for (; i + 2 < end; i += 4) {
        int s0 = d_csr1[i], s1 = d_csr1[i+2];
        float w0 = __expf(lrelu(__ldg(&d_as1[s0*NH + w]) + ad));
        float w1 = __expf(lrelu(__ldg(&d_as1[s1*NH + w]) + ad));
        ssum += w0 + w1;
        const float* h0 = &d_h1[s0*(NH*NO) + w*NO];
        const float* h1 = &d_h1[s1*(NH*NO) + w*NO];
        a0 += w0 * h0[c0];
        b0 += w1 * h1[c0];
        if (has1) { a1 += w0 * h0[c1]; b1 += w1 * h1[c1]; }
    }
    if (i < end) {
        int s0 = d_csr1[i];
        float w0 = __expf(lrelu(__ldg(&d_as1[s0*NH + w]) + ad));
        ssum += w0;
        const float* h0 = &d_h1[s0*(NH*NO) + w*NO];
        a0 += w0 * h0[c0];
        if (has1) a1 += w0 * h0[c1];
    }
    a0 += b0; a1 += b1;
    if (lane == 0) atomicAdd(&ssum_sh[w], ssum);
    __syncthreads();
    float inv = 0.25f / (ssum_sh[w] + 1e-16f);
    atomicAdd(&so[c0], a0 * inv);
    if (has1) atomicAdd(&so[c1], a1 * inv);
    __syncthreads();
    if (t < NO) {
        float v = so[t] + bias[t];
        so[t] = v;
        d_x1o[n*NO + t] = v;
    }
    __syncthreads();
    float p = 0.f;
    for (int r = wp; r < NO; r += 8) {
        float xr = so[r];
        float acc = __ldg(&d_M[r*NO + c0]) * so[c0];
        if (has1) acc += __ldg(&d_M[r*NO + c1]) * so[c1];
        p += acc * xr;
    }
    red[t] = p;
    __syncthreads();
    if (t < 128) red[t] += red[t+128];
    __syncthreads();
    if (t < 64) red[t] += red[t+64];
    __syncthreads();
    if (t < 32) {
        float v = red[t] + red[t+32];
        v = warp_sum(v);
        if (t == 0) d_q1h[n] = -0.5f * v;
    }
}

// ==== D: attention (8 f's/block, c-outer dot) -> barrier -> GAT2 aggregate ====
__global__ void __launch_bounds__(256, 4) kD(
        const float* __restrict__ lin,
        const float* __restrict__ asrc, const float* __restrict__ adst,
        const float* __restrict__ bias, float* __restrict__ out) {
    int t = threadIdx.x;
    __shared__ float xt[PAST*51];      // 26112 B
    __shared__ float x2s[8*NO];
    __shared__ float zs[8*NO];
    __shared__ float qh[PAST];
    __shared__ float yv[PAST];
    __shared__ float s_tmp[8];
    __shared__ unsigned msk[8*4];

    {   // ---- attn phase: vb == blockIdx.x, 8 f's ----
        int vb = blockIdx.x;
        int b = vb >> 3, q = vb & 7;
        int fbase = q * 8;

        const float* x1src = d_x1o + (size_t)b*PAST*NO;
        for (int idx = t; idx < PAST*NO; idx += 256) {
            int p = idx / NO, c = idx % NO;
            xt[p*51 + c] = x1src[idx];
        }
        for (int idx = t; idx < 8*NO; idx += 256) {
            int fl = idx / NO, c = idx % NO;
            int nn = (b*FUT + fbase + fl)*NO + c;
            x2s[idx] = d_x2[nn];
            zs[idx]  = d_z2[nn];
        }
        if (t < PAST) { qh[t] = d_q1h[b*PAST + t]; yv[t] = d_y[b*PAST + t]; }
        if (t < 32)   msk[t] = d_maskw[(fbase + (t>>2))*4 + (t&3)];
        __syncthreads();

        int fl = t >> 5;          // warp per f
        int psub = t & 31;
        const float* zrow = zs + fl*NO;
        // c-outer dot: 4 independent accumulators, zrow loaded once per c
        const float* xr0 = xt + (psub +  0)*51;
        const float* xr1 = xt + (psub + 32)*51;
        const float* xr2 = xt + (psub + 64)*51;
        const float* xr3 = xt + (psub + 96)*51;
        float a0 = 0.f, a1 = 0.f, a2 = 0.f, a3 = 0.f;
        #pragma unroll
        for (int c = 0; c < NO; c++) {
            float zc = zrow[c];
            a0 += zc * xr0[c];
            a1 += zc * xr1[c];
            a2 += zc * xr2[c];
            a3 += zc * xr3[c];
        }
        float sex = 0.f, swv = 0.f;
        {
            float lg, ex;
            lg = qh[psub]      + a0; ex = ((msk[fl*4+0] >> psub) & 1u) ? __expf(lg) : 0.f; sex += ex; swv += ex * yv[psub];
            lg = qh[psub + 32] + a1; ex = ((msk[fl*4+1] >> psub) & 1u) ? __expf(lg) : 0.f; sex += ex; swv += ex * yv[psub + 32];
            lg = qh[psub + 64] + a2; ex = ((msk[fl*4+2] >> psub) & 1u) ? __expf(lg) : 0.f; sex += ex; swv += ex * yv[psub + 64];
            lg = qh[psub + 96] + a3; ex = ((msk[fl*4+3] >> psub) & 1u) ? __expf(lg) : 0.f; sex += ex; swv += ex * yv[psub + 96];
        }
        sex = warp_sum(sex);
        swv = warp_sum(swv);
        if (psub == 0) s_tmp[fl] = swv / (sex + 1e-16f);
        __syncthreads();

        // GAT2 linear: 32 outputs (8 f x 4 h), 8 threads each
        {
            int o = t >> 3, sub = t & 7;   // o: 0..31
            int fl2 = o >> 2, h = o & 3;
            const float* xr = x2s + fl2*NO;
            float acc = 0.f;
            for (int k = sub; k < NO; k += 8) acc += xr[k] * __ldg(&lin[k*NH + h]);
            acc += __shfl_xor_sync(0xffffffffu, acc, 4);
            acc += __shfl_xor_sync(0xffffffffu, acc, 2);
            acc += __shfl_xor_sync(0xffffffffu, acc, 1);
            if (sub == 0) {
                int n = b*FUT + fbase + fl2;
                float v = acc + s_tmp[fl2] * __ldg(&lin[NO*NH + h]);
                d_h2[n*NH + h]  = v;
                d_as2[n*NH + h] = v * asrc[h];
                d_ad2[n*NH + h] = v * adst[h];
            }
        }
    }
    grid_barrier();
    // ---- agg2 phase: 8 nodes per block, 1:1 ----
    {
        int n = blockIdx.x*8 + (t >> 5);
        int lane = t & 31;
        int beg = n*PAD;
        int cnt = d_cur2[n];
        __syncwarp();
        if (lane == 0) d_cur2[n] = 0;   // restore for next replay
        int end = beg + cnt;
        float4 adv = *(const float4*)&d_ad2[n*NH];
        float ss0=0,ss1=0,ss2=0,ss3=0, ws0=0,ws1=0,ws2=0,ws3=0;
        for (int i = beg + lane; i < end; i += 32) {
            int s = d_csr2[i];
            float4 av = *(const float4*)&d_as2[s*NH];
            float4 hv = *(const float4*)&d_h2[s*NH];
            float e0 = __expf(lrelu(av.x + adv.x));
            float e1 = __expf(lrelu(av.y + adv.y));
            float e2 = __expf(lrelu(av.z + adv.z));
            float e3 = __expf(lrelu(av.w + adv.w));
            ss0+=e0; ws0+=e0*hv.x;
            ss1+=e1; ws1+=e1*hv.y;
            ss2+=e2; ws2+=e2*hv.z;
            ss3+=e3; ws3+=e3*hv.w;
        }
        ss0=warp_sum(ss0); ws0=warp_sum(ws0);
        ss1=warp_sum(ss1); ws1=warp_sum(ws1);
        ss2=warp_sum(ss2); ws2=warp_sum(ws2);
        ss3=warp_sum(ss3); ws3=warp_sum(ws3);
        if (lane == 0) {
            float total = 0.25f*ws0/(ss0+1e-16f) + 0.25f*ws1/(ss1+1e-16f)
                        + 0.25f*ws2/(ss2+1e-16f) + 0.25f*ws3/(ss3+1e-16f);
            out[n] = total + bias[0];
        }
    }
}

// ================= launch: 3 kernels, single stream, no events =================
extern "C" void kernel_launch(void* const* d_in, const int* in_sizes, int n_in,
                              void* d_out, int out_size) {
    const int*   cat1   = (const int*)  d_in[0];
    const float* num1   = (const float*)d_in[1];
    const int*   cat2   = (const int*)  d_in[2];
    const float* num2   = (const float*)d_in[3];
    const int*   e1     = (const int*)  d_in[4];
    const int*   e2     = (const int*)  d_in[5];
    const int*   A      = (const int*)  d_in[6];
    const float* emb0   = (const float*)d_in[7];
    const float* emb1   = (const float*)d_in[8];
    const float* emb2   = (const float*)d_in[9];
    const float* g1_lin = (const float*)d_in[10];
    const float* g1_as  = (const float*)d_in[11];
    const float* g1_ad  = (const float*)d_in[12];
    const float* g1_b   = (const float*)d_in[13];
    const float* g2_lin = (const float*)d_in[14];
    const float* g2_as  = (const float*)d_in[15];
    const float* g2_ad  = (const float*)d_in[16];
    const float* g2_b   = (const float*)d_in[17];
    const float* W      = (const float*)d_in[18];
    float* out = (float*)d_out;

    kA<<<AGRID, 256>>>(cat1, num1, cat2, num2, e1, e2, A, emb0, emb1, emb2,
                       g1_lin, g1_as, g1_ad, W);
    kAgg1<<<N1 + Z2B, 256>>>(g1_b);
    kD<<<DGRID, 256>>>(g2_lin, g2_as, g2_ad, g2_b, out);
}

// round 17
// speedup vs baseline: 1.1719x; 1.1719x over previous
#include <cuda_runtime.h>
#include <math.h>

#define BN   64
#define PAST 128
#define FUT  64
#define NF   51
#define NO   50
#define NH   4
#define N1   (BN*PAST)   /* 8192 */
#define N2   (BN*FUT)    /* 4096 */
#define E1N  (N1*16)
#define E2N  (N2*16)
#define T1   (E1N+N1)    /* 139264 */
#define T2   (E2N+N2)    /* 69632 */
#define PAD  64          /* bucket slots per node (max degree ~34) */
#define GNB  8           /* nodes per gemm block */
#define GGRID (N1/GNB)   /* 1024 */
#define X2B  (N2/16)     /* 256 x2-pre blocks */
#define MB   4
#define SCB  ((T1+T2+255)/256)   /* 816 scatter blocks */
#define RGRID (SCB + X2B + MB + 1)
#define DGRID 512
#define Z2PB 20
#define Z2B  ((N2+Z2PB-1)/Z2PB)  /* 205 */

// ---------------- scratch ----------------
__device__ float d_y  [N1];
__device__ float d_x2 [N2*NO];
__device__ float d_h1 [N1*NH*NO];
__device__ __align__(16) float d_as1[N1*NH];
__device__ __align__(16) float d_ad1[N1*NH];
__device__ float d_x1o[N1*NO];
__device__ float d_M  [NO*NO];
__device__ float d_q1h[N1];
__device__ float d_z2 [N2*NO];
__device__ __align__(16) float d_h2 [N2*NH];
__device__ __align__(16) float d_as2[N2*NH];
__device__ __align__(16) float d_ad2[N2*NH];
__device__ unsigned d_maskw[FUT*4];
__device__ int d_cur1[N1];           // zero at load; consumer restores per call
__device__ int d_csr1[N1*PAD];       // padded buckets
__device__ int d_cur2[N2];
__device__ int d_csr2[N2*PAD];

// grid barrier (monotonic flag: replay-safe). Used only by kD.
__device__ unsigned g_barcnt = 0;
__device__ unsigned g_barflag = 0;

__device__ __forceinline__ void grid_barrier() {
    __syncthreads();
    if (threadIdx.x == 0) {
        unsigned old = *((volatile unsigned*)&g_barflag);
        __threadfence();
        unsigned a = atomicAdd(&g_barcnt, 1u);
        if (a == gridDim.x - 1) {
            atomicExch(&g_barcnt, 0u);
            __threadfence();
            atomicExch(&g_barflag, old + 1u);
        } else {
            while (*((volatile unsigned*)&g_barflag) == old) __nanosleep(64);
        }
        __threadfence();
    }
    __syncthreads();
}

__device__ __forceinline__ float warp_sum(float v) {
    #pragma unroll
    for (int o = 16; o; o >>= 1) v += __shfl_xor_sync(0xffffffffu, v, o);
    return v;
}
__device__ __forceinline__ float lrelu(float x) { return x > 0.f ? x : 0.2f * x; }

// ========== kGemm: GAT1 linear, 8 nodes/block, transposed xs (LDS.128 bcast) ==========
__global__ void kGemm(const int* __restrict__ cat1, const float* __restrict__ num1,
                      const float* __restrict__ e0w, const float* __restrict__ e1w,
                      const float* __restrict__ e2w,
                      const float* __restrict__ lin, const float* __restrict__ asrc,
                      const float* __restrict__ adst) {
    __shared__ __align__(16) float xs[NF*GNB];   // transposed: xs[k*8 + j]
    __shared__ float hs[GNB*NH*NO];
    int t = threadIdx.x;
    int n0 = blockIdx.x*GNB;
    for (int idx = t; idx < GNB*NF; idx += 256) {
        int j = idx / NF, k = idx % NF, n = n0 + j;
        float v;
        if      (k < 16) v = e0w[cat1[n*3+0]*16 + k];
        else if (k < 24) v = e1w[cat1[n*3+1]*8  + (k-16)];
        else if (k < 48) v = e2w[cat1[n*3+2]*24 + (k-24)];
        else             v = num1[n*3 + (k-48)];
        xs[k*GNB + j] = v;
        if (k == NF-1) d_y[n] = v;
    }
    __syncthreads();
    if (t < NH*NO) {
        float acc[GNB];
        #pragma unroll
        for (int j = 0; j < GNB; j++) acc[j] = 0.f;
        #pragma unroll 3
        for (int k = 0; k < NF; k++) {
            float l = __ldg(&lin[k*(NH*NO) + t]);
            float4 xa = *(const float4*)&xs[k*GNB];
            float4 xb = *(const float4*)&xs[k*GNB + 4];
            acc[0] += xa.x * l; acc[1] += xa.y * l;
            acc[2] += xa.z * l; acc[3] += xa.w * l;
            acc[4] += xb.x * l; acc[5] += xb.y * l;
            acc[6] += xb.z * l; acc[7] += xb.w * l;
        }
        #pragma unroll
        for (int j = 0; j < GNB; j++) {
            d_h1[(n0+j)*(NH*NO) + t] = acc[j];
            hs[j*(NH*NO) + t] = acc[j];
        }
    }
    __syncthreads();
    if (t < GNB*8) {
        int j = t >> 3, r = t & 7, head = r & 3;
        const float* att = (r < 4) ? asrc : adst;
        float a = 0.f;
        #pragma unroll
        for (int c = 0; c < NO; c++)
            a += hs[j*(NH*NO) + head*NO + c] * att[head*NO + c];
        if (r < 4) d_as1[(n0+j)*NH + head] = a;
        else       d_ad1[(n0+j)*NH + head] = a;
    }
}

// ========== kRest: scatter | x2 pre | M | mask (all input-only, side stream) ==========
__global__ void kRest(const int* __restrict__ cat2, const float* __restrict__ num2,
                      const int* __restrict__ e1, const int* __restrict__ e2,
                      const int* __restrict__ A,
                      const float* __restrict__ e0w, const float* __restrict__ e1w,
                      const float* __restrict__ e2w, const float* __restrict__ W) {
    int bb = blockIdx.x, t = threadIdx.x;
    if (bb < SCB) {
        int i = bb*256 + t;
        if (i < T1) {
            int s, d;
            if (i < E1N) { s = e1[i]; d = e1[E1N + i]; }
            else         { s = d = i - E1N; }
            int pos = atomicAdd(&d_cur1[d], 1);
            d_csr1[d*PAD + pos] = s;
        } else {
            int j = i - T1;
            if (j < T2) {
                int s, d;
                if (j < E2N) { s = e2[j]; d = e2[E2N + j]; }
                else         { s = d = j - E2N; }
                int pos = atomicAdd(&d_cur2[d], 1);
                d_csr2[d*PAD + pos] = s;
            }
        }
        return;
    }
    bb -= SCB;
    if (bb < X2B) {
        int base = bb*16;
        for (int idx = t; idx < 16*NO; idx += 256) {
            int ln = idx / NO, c = idx % NO;
            int n = base + ln;
            float v;
            if      (c < 16) v = e0w[cat2[n*3+0]*16 + c];
            else if (c < 24) v = e1w[cat2[n*3+1]*8  + (c-16)];
            else if (c < 48) v = e2w[cat2[n*3+2]*24 + (c-24)];
            else             v = num2[n*3 + (c-48)];
            d_x2[n*NO + c] = v;
        }
        return;
    }
    bb -= X2B;
    if (bb < MB) {
        int lo = bb*625, hi = lo + 625;
        for (int idx = lo + t; idx < hi; idx += 256) {
            int i = idx / NO, j = idx % NO;
            float s = 0.f;
            #pragma unroll
            for (int k = 0; k < 64; k++) s += __ldg(&W[i*64+k]) * __ldg(&W[j*64+k]);
            d_M[idx] = 2.f * s;
        }
        return;
    }
    {
        int f = t >> 2, wd = t & 3;
        unsigned u = 0;
        for (int i = 0; i < 32; i++)
            if (A[(wd*32+i)*(PAST+FUT) + PAST + f]) u |= (1u << i);
        d_maskw[f*4 + wd] = u;
    }
}

// ==== kAgg1: GAT1 aggregate (blocks < N1) | z2 = M @ x2 (extra blocks) ====
__global__ void kAgg1(const float* __restrict__ bias) {
    __shared__ float sbuf[NO*NO + Z2PB*NO];   // 14 KB union
    int n = blockIdx.x;
    int t = threadIdx.x;

    if (n >= N1) {
        int base = (n - N1) * Z2PB;
        float* Ms  = sbuf;
        float* x2s = sbuf + NO*NO;
        for (int idx = t; idx < NO*NO; idx += 256) Ms[idx] = d_M[idx];
        for (int idx = t; idx < Z2PB*NO; idx += 256) {
            int gl = base*NO + idx;
            x2s[idx] = (gl < N2*NO) ? d_x2[gl] : 0.f;
        }
        __syncthreads();
        for (int idx = t; idx < Z2PB*NO; idx += 256) {
            int ln = idx / NO, c = idx % NO;
            int node = base + ln;
            if (node < N2) {
                float z = 0.f;
                #pragma unroll
                for (int j = 0; j < NO; j++) z += Ms[c*NO + j] * x2s[ln*NO + j];
                d_z2[node*NO + c] = z;
            }
        }
        return;
    }

    int wp = t >> 5;
    int w  = wp >> 1;
    int eh = wp & 1;
    int lane = t & 31;
    int beg = n*PAD;
    int end = beg + d_cur1[n];     // degree from scatter
    float ad = d_ad1[n*NH + w];

    float* so      = sbuf;          // 50
    float* ssum_sh = sbuf + 64;     // 4
    float* red     = sbuf + 96;     // 256
    if (t < NO) so[t] = 0.f;
    if (t < NH) ssum_sh[t] = 0.f;
    __syncthreads();
    if (t == 0) d_cur1[n] = 0;      // restore for next replay

    float ssum = 0.f, a0 = 0.f, a1 = 0.f, b0 = 0.f, b1 = 0.f;
    int c0 = lane, c1 = lane + 32;
    bool has1 = (c1 < NO);
    int i = beg + eh;
    for (; i + 2 < end; i += 4) {
        int s0 = d_csr1[i], s1 = d_csr1[i+2];
        float w0 = __expf(lrelu(__ldg(&d_as1[s0*NH + w]) + ad));
        float w1 = __expf(lrelu(__ldg(&d_as1[s1*NH + w]) + ad));
        ssum += w0 + w1;
        const float* h0 = &d_h1[s0*(NH*NO) + w*NO];
        const float* h1 = &d_h1[s1*(NH*NO) + w*NO];
        a0 += w0 * h0[c0];
        b0 += w1 * h1[c0];
        if (has1) { a1 += w0 * h0[c1]; b1 += w1 * h1[c1]; }
    }
    if (i < end) {
        int s0 = d_csr1[i];
        float w0 = __expf(lrelu(__ldg(&d_as1[s0*NH + w]) + ad));
        ssum += w0;
        const float* h0 = &d_h1[s0*(NH*NO) + w*NO];
        a0 += w0 * h0[c0];
        if (has1) a1 += w0 * h0[c1];
    }
    a0 += b0; a1 += b1;
    if (lane == 0) atomicAdd(&ssum_sh[w], ssum);
    __syncthreads();
    float inv = 0.25f / (ssum_sh[w] + 1e-16f);
    atomicAdd(&so[c0], a0 * inv);
    if (has1) atomicAdd(&so[c1], a1 * inv);
    __syncthreads();
    if (t < NO) {
        float v = so[t] + bias[t];
        so[t] = v;
        d_x1o[n*NO + t] = v;
    }
    __syncthreads();
    float p = 0.f;
    for (int r = wp; r < NO; r += 8) {
        float xr = so[r];
        float acc = __ldg(&d_M[r*NO + c0]) * so[c0];
        if (has1) acc += __ldg(&d_M[r*NO + c1]) * so[c1];
        p += acc * xr;
    }
    red[t] = p;
    __syncthreads();
    if (t < 128) red[t] += red[t+128];
    __syncthreads();
    if (t < 64) red[t] += red[t+64];
    __syncthreads();
    if (t < 32) {
        float v = red[t] + red[t+32];
        v = warp_sum(v);
        if (t == 0) d_q1h[n] = -0.5f * v;
    }
}

// ==== kD: attention (8 f's/block, c-outer dot) -> barrier -> GAT2 aggregate ====
__global__ void __launch_bounds__(256, 4) kD(
        const float* __restrict__ lin,
        const float* __restrict__ asrc, const float* __restrict__ adst,
        const float* __restrict__ bias, float* __restrict__ out) {
    int t = threadIdx.x;
    __shared__ float xt[PAST*51];      // 26112 B
    __shared__ float x2s[8*NO];
    __shared__ float zs[8*NO];
    __shared__ float qh[PAST];
    __shared__ float yv[PAST];
    __shared__ float s_tmp[8];
    __shared__ unsigned msk[8*4];

    {   // ---- attn phase: vb == blockIdx.x, 8 f's ----
        int vb = blockIdx.x;
        int b = vb >> 3, q = vb & 7;
        int fbase = q * 8;

        const float* x1src = d_x1o + (size_t)b*PAST*NO;
        for (int idx = t; idx < PAST*NO; idx += 256) {
            int p = idx / NO, c = idx % NO;
            xt[p*51 + c] = x1src[idx];
        }
        for (int idx = t; idx < 8*NO; idx += 256) {
            int fl = idx / NO, c = idx % NO;
            int nn = (b*FUT + fbase + fl)*NO + c;
            x2s[idx] = d_x2[nn];
            zs[idx]  = d_z2[nn];
        }
        if (t < PAST) { qh[t] = d_q1h[b*PAST + t]; yv[t] = d_y[b*PAST + t]; }
        if (t < 32)   msk[t] = d_maskw[(fbase + (t>>2))*4 + (t&3)];
        __syncthreads();

        int fl = t >> 5;          // warp per f
        int psub = t & 31;
        const float* zrow = zs + fl*NO;
        const float* xr0 = xt + (psub +  0)*51;
        const float* xr1 = xt + (psub + 32)*51;
        const float* xr2 = xt + (psub + 64)*51;
        const float* xr3 = xt + (psub + 96)*51;
        float a0 = 0.f, a1 = 0.f, a2 = 0.f, a3 = 0.f;
        #pragma unroll
        for (int c = 0; c < NO; c++) {
            float zc = zrow[c];
            a0 += zc * xr0[c];
            a1 += zc * xr1[c];
            a2 += zc * xr2[c];
            a3 += zc * xr3[c];
        }
        float sex = 0.f, swv = 0.f;
        {
            float lg, ex;
            lg = qh[psub]      + a0; ex = ((msk[fl*4+0] >> psub) & 1u) ? __expf(lg) : 0.f; sex += ex; swv += ex * yv[psub];
            lg = qh[psub + 32] + a1; ex = ((msk[fl*4+1] >> psub) & 1u) ? __expf(lg) : 0.f; sex += ex; swv += ex * yv[psub + 32];
            lg = qh[psub + 64] + a2; ex = ((msk[fl*4+2] >> psub) & 1u) ? __expf(lg) : 0.f; sex += ex; swv += ex * yv[psub + 64];
            lg = qh[psub + 96] + a3; ex = ((msk[fl*4+3] >> psub) & 1u) ? __expf(lg) : 0.f; sex += ex; swv += ex * yv[psub + 96];
        }
        sex = warp_sum(sex);
        swv = warp_sum(swv);
        if (psub == 0) s_tmp[fl] = swv / (sex + 1e-16f);
        __syncthreads();

        {
            int o = t >> 3, sub = t & 7;
            int fl2 = o >> 2, h = o & 3;
            const float* xr = x2s + fl2*NO;
            float acc = 0.f;
            for (int k = sub; k < NO; k += 8) acc += xr[k] * __ldg(&lin[k*NH + h]);
            acc += __shfl_xor_sync(0xffffffffu, acc, 4);
            acc += __shfl_xor_sync(0xffffffffu, acc, 2);
            acc += __shfl_xor_sync(0xffffffffu, acc, 1);
            if (sub == 0) {
                int n = b*FUT + fbase + fl2;
                float v = acc + s_tmp[fl2] * __ldg(&lin[NO*NH + h]);
                d_h2[n*NH + h]  = v;
                d_as2[n*NH + h] = v * asrc[h];
                d_ad2[n*NH + h] = v * adst[h];
            }
        }
    }
    grid_barrier();
    // ---- agg2 phase: 8 nodes per block, 1:1 ----
    {
        int n = blockIdx.x*8 + (t >> 5);
        int lane = t & 31;
        int beg = n*PAD;
        int cnt = d_cur2[n];
        __syncwarp();
        if (lane == 0) d_cur2[n] = 0;   // restore for next replay
        int end = beg + cnt;
        float4 adv = *(const float4*)&d_ad2[n*NH];
        float ss0=0,ss1=0,ss2=0,ss3=0, ws0=0,ws1=0,ws2=0,ws3=0;
        for (int i = beg + lane; i < end; i += 32) {
            int s = d_csr2[i];
            float4 av = *(const float4*)&d_as2[s*NH];
            float4 hv = *(const float4*)&d_h2[s*NH];
            float e0 = __expf(lrelu(av.x + adv.x));
            float e1 = __expf(lrelu(av.y + adv.y));
            float e2 = __expf(lrelu(av.z + adv.z));
            float e3 = __expf(lrelu(av.w + adv.w));
            ss0+=e0; ws0+=e0*hv.x;
            ss1+=e1; ws1+=e1*hv.y;
            ss2+=e2; ws2+=e2*hv.z;
            ss3+=e3; ws3+=e3*hv.w;
        }
        ss0=warp_sum(ss0); ws0=warp_sum(ws0);
        ss1=warp_sum(ss1); ws1=warp_sum(ws1);
        ss2=warp_sum(ss2); ws2=warp_sum(ws2);
        ss3=warp_sum(ss3); ws3=warp_sum(ws3);
        if (lane == 0) {
            float total = 0.25f*ws0/(ss0+1e-16f) + 0.25f*ws1/(ss1+1e-16f)
                        + 0.25f*ws2/(ss2+1e-16f) + 0.25f*ws3/(ss3+1e-16f);
            out[n] = total + bias[0];
        }
    }
}

// ================= launch: gemm ∥ rest -> agg1 -> D =================
extern "C" void kernel_launch(void* const* d_in, const int* in_sizes, int n_in,
                              void* d_out, int out_size) {
    const int*   cat1   = (const int*)  d_in[0];
    const float* num1   = (const float*)d_in[1];
    const int*   cat2   = (const int*)  d_in[2];
    const float* num2   = (const float*)d_in[3];
    const int*   e1     = (const int*)  d_in[4];
    const int*   e2     = (const int*)  d_in[5];
    const int*   A      = (const int*)  d_in[6];
    const float* emb0   = (const float*)d_in[7];
    const float* emb1   = (const float*)d_in[8];
    const float* emb2   = (const float*)d_in[9];
    const float* g1_lin = (const float*)d_in[10];
    const float* g1_as  = (const float*)d_in[11];
    const float* g1_ad  = (const float*)d_in[12];
    const float* g1_b   = (const float*)d_in[13];
    const float* g2_lin = (const float*)d_in[14];
    const float* g2_as  = (const float*)d_in[15];
    const float* g2_ad  = (const float*)d_in[16];
    const float* g2_b   = (const float*)d_in[17];
    const float* W      = (const float*)d_in[18];
    float* out = (float*)d_out;

    static cudaStream_t s1 = nullptr;
    static cudaEvent_t evF = nullptr, evB = nullptr;
    if (!s1) {
        cudaStreamCreateWithFlags(&s1, cudaStreamNonBlocking);
        cudaEventCreateWithFlags(&evF, cudaEventDisableTiming);
        cudaEventCreateWithFlags(&evB, cudaEventDisableTiming);
    }

    cudaEventRecord(evF, 0);
    cudaStreamWaitEvent(s1, evF, 0);

    // side: scatter + x2pre + M + mask (input-only)
    kRest<<<RGRID, 256, 0, s1>>>(cat2, num2, e1, e2, A, emb0, emb1, emb2, W);
    cudaEventRecord(evB, s1);

    // main chain
    kGemm<<<GGRID, 256>>>(cat1, num1, emb0, emb1, emb2, g1_lin, g1_as, g1_ad);
    cudaStreamWaitEvent(0, evB, 0);
    kAgg1<<<N1 + Z2B, 256>>>(g1_b);
    kD<<<DGRID, 256>>>(g2_lin, g2_as, g2_ad, g2_b, out);
}